// round 17
// baseline (speedup 1.0000x reference)
#include <cuda_runtime.h>
#include <cuda_fp16.h>
#include <cstdint>
#include <math.h>

// Batched Stiefel optimizer step via Cholesky-QR.
// Round 17: fp16 STORAGE for B, Asym, V (each was already rounded to fp16 by
// every consumer's loader — move the rounding to the producer). Bit-identical
// math to Round 16; halves operand traffic for GEMM3-B, GEMM4 (both sides),
// GEMM6 (both sides) and deletes cvt ALU from those loaders.

#define NB 128
#define RR 2304
#define CC 256

static constexpr int NGRP = 8;
static constexpr int GB   = NB / NGRP;   // 16 batches per group

__device__ float  g_A[(size_t)NB * CC * CC];     // A = M^T Graw; later S = B^T B (fp32)
__device__ __half g_As[(size_t)NB * CC * CC];    // sym(A) (fp16)
__device__ __half g_Bh[(size_t)NB * RR * CC];    // B = M + P (fp16)
__device__ __half g_Vh[(size_t)NB * CC * CC];    // V = R^{-1} dense upper (fp16)

// ---------------------------------------------------------------------------
static constexpr int HROWB = 80;                 // smem row bytes; conflict-free
static constexpr int BUF = 128 * HROWB;          // 10240 B per operand buffer
static constexpr int OFF_AH = 0;
static constexpr int OFF_BH = BUF;
static constexpr int STAGE_BYTES = 2 * BUF;      // 20480
static constexpr int GEMM_SMEM = 67840;          // >= MODE3 transpose (67584)

__device__ __forceinline__ uint32_t smem_u32(const void* p) {
    uint32_t a;
    asm("{ .reg .u64 t; cvta.to.shared.u64 t, %1; cvt.u32.u64 %0, t; }"
        : "=r"(a) : "l"(p));
    return a;
}

__device__ __forceinline__ void mma16816(float* c, const uint32_t* a, const uint32_t* b) {
    asm volatile(
        "mma.sync.aligned.m16n8k16.row.col.f32.f16.f16.f32 "
        "{%0,%1,%2,%3}, {%4,%5,%6,%7}, {%8,%9}, {%0,%1,%2,%3};"
        : "+f"(c[0]), "+f"(c[1]), "+f"(c[2]), "+f"(c[3])
        : "r"(a[0]), "r"(a[1]), "r"(a[2]), "r"(a[3]), "r"(b[0]), "r"(b[1]));
}

__device__ __forceinline__ void ldsm4(uint32_t& r0, uint32_t& r1, uint32_t& r2,
                                      uint32_t& r3, uint32_t addr) {
    asm volatile("ldmatrix.sync.aligned.m8n8.x4.shared.b16 {%0,%1,%2,%3}, [%4];"
                 : "=r"(r0), "=r"(r1), "=r"(r2), "=r"(r3) : "r"(addr));
}

__device__ __forceinline__ uint32_t rnd2(float x0, float x1) {
    __half h0 = __float2half_rn(x0), h1 = __float2half_rn(x1);
    return ((uint32_t)__half_as_ushort(h1) << 16) | __half_as_ushort(h0);
}
__device__ __forceinline__ uint32_t pack2(const __half* p, int stride) {
    return ((uint32_t)__half_as_ushort(p[stride]) << 16) | __half_as_ushort(p[0]);
}

// ---------------------------------------------------------------------------
// Unified GEMM. 128x128 CTA tile, fp16 MMA (fp32 acc), ldmatrix.
// AH/BH: operand stored as fp16 in gmem (no per-tile rounding needed).
// MODE 0 (TN, K=KTOT): D -> Op[i0+m][j0+n] (fp32). TRI: lower tiles only.
// MODE 2 (NN, K=256):  Op = Ag + a*(D - E1 - E2), written fp16 (B-build)
// MODE 3 (NN, K=256):  Op[j0+n][i0+m] = D (fp32). B upper-tri: j0=0 -> K=128.
// ---------------------------------------------------------------------------
template <int MODE, int KTOT, bool TRI, bool AH, bool BH>
__global__ void __launch_bounds__(256, 2)
k_gemm(const void* __restrict__ Ag_, const void* __restrict__ Bg_,
       const float* __restrict__ E1_, const float* __restrict__ E2_,
       const float* __restrict__ lr, const float* __restrict__ s_lr,
       void* __restrict__ Out_)
{
    extern __shared__ char dsm[];
    const int tid = threadIdx.x;
    const int lane = tid & 31, warp = tid >> 5;
    const int wm = warp & 3, wn = warp >> 2;
    const int b = blockIdx.z;

    int i0, j0;
    if (TRI) {
        int bx = blockIdx.x;            // 0:(0,0) 1:(1,0) 2:(1,1)
        i0 = (bx >= 1) ? 128 : 0;
        j0 = (bx == 2) ? 128 : 0;
    } else {
        j0 = blockIdx.x * 128;
        i0 = blockIdx.y * 128;
    }

    const size_t bigS = (size_t)RR * CC, smlS = (size_t)CC * CC;
    const size_t strB = (MODE == 0) ? bigS : smlS;
    const float*  Agf = (const float*)Ag_ + (size_t)b * bigS;   // valid if !AH
    const __half* Agh = (const __half*)Ag_ + (size_t)b * bigS;  // valid if AH
    const float*  Bgf = (const float*)Bg_ + (size_t)b * strB;
    const __half* Bgh = (const __half*)Bg_ + (size_t)b * strB;

    const uint32_t base32 = smem_u32(dsm);

    float acc[2][8][4] = {};
    float ra[16], rb[16];
    uint32_t rau[8], rbu[8];

    constexpr int NC = KTOT / 32;
    const int ncr = (MODE == 3 && j0 == 0) ? (NC / 2) : NC;

    auto LOADR = [&](int c) {
        const int k0 = c * 32;
        if (MODE == 0) {
#pragma unroll
            for (int it = 0; it < 4; ++it) {
                int idx = tid + it * 256;
                int m = idx & 127, kq = idx >> 7;
                if (AH) {
                    const __half* p = Agh + (size_t)(k0 + kq * 4) * CC + i0 + m;
                    rau[2 * it]     = pack2(p, CC);
                    rau[2 * it + 1] = pack2(p + 2 * CC, CC);
                } else {
#pragma unroll
                    for (int j = 0; j < 4; ++j)
                        ra[it * 4 + j] = Agf[(size_t)(k0 + kq * 4 + j) * CC + i0 + m];
                }
            }
        } else {
#pragma unroll
            for (int it = 0; it < 4; ++it) {
                int idx = tid + it * 256;
                int kq = idx & 7, m = idx >> 3;
                if (AH) {
                    uint2 v = *(const uint2*)(Agh + (size_t)(i0 + m) * CC + k0 + kq * 4);
                    rau[2 * it] = v.x; rau[2 * it + 1] = v.y;
                } else {
                    float4 v = *(const float4*)(Agf + (size_t)(i0 + m) * CC + k0 + kq * 4);
                    ra[it * 4 + 0] = v.x; ra[it * 4 + 1] = v.y;
                    ra[it * 4 + 2] = v.z; ra[it * 4 + 3] = v.w;
                }
            }
        }
#pragma unroll
        for (int it = 0; it < 4; ++it) {
            int idx = tid + it * 256;
            int n = idx & 127, kq = idx >> 7;
            if (BH) {
                const __half* p = Bgh + (size_t)(k0 + kq * 4) * CC + j0 + n;
                rbu[2 * it]     = pack2(p, CC);
                rbu[2 * it + 1] = pack2(p + 2 * CC, CC);
            } else {
#pragma unroll
                for (int j = 0; j < 4; ++j)
                    rb[it * 4 + j] = Bgf[(size_t)(k0 + kq * 4 + j) * CC + j0 + n];
            }
        }
    };

    auto STORER = [&](int s) {
        char* st = dsm + s * STAGE_BYTES;
#pragma unroll
        for (int it = 0; it < 4; ++it) {
            int idx = tid + it * 256;
            int m, kq;
            if (MODE == 0) { m = idx & 127; kq = idx >> 7; }
            else           { kq = idx & 7;  m = idx >> 3; }
            uint2 v;
            if (AH) v = make_uint2(rau[2 * it], rau[2 * it + 1]);
            else    v = make_uint2(rnd2(ra[it * 4 + 0], ra[it * 4 + 1]),
                                   rnd2(ra[it * 4 + 2], ra[it * 4 + 3]));
            *(uint2*)(st + OFF_AH + m * HROWB + kq * 8) = v;
        }
#pragma unroll
        for (int it = 0; it < 4; ++it) {
            int idx = tid + it * 256;
            int n = idx & 127, kq = idx >> 7;
            uint2 v;
            if (BH) v = make_uint2(rbu[2 * it], rbu[2 * it + 1]);
            else    v = make_uint2(rnd2(rb[it * 4 + 0], rb[it * 4 + 1]),
                                   rnd2(rb[it * 4 + 2], rb[it * 4 + 3]));
            *(uint2*)(st + OFF_BH + n * HROWB + kq * 8) = v;
        }
    };

    auto COMPUTE = [&](int s) {
        const uint32_t st = base32 + s * STAGE_BYTES;
#pragma unroll
        for (int ks = 0; ks < 2; ++ks) {
            const uint32_t kb = ks * 32;
            uint32_t ah[2][4], bh[8][2];
            const int arow_off = (lane & 15);
            const uint32_t achunk = kb + ((lane >> 4) << 4);
#pragma unroll
            for (int mi = 0; mi < 2; ++mi) {
                uint32_t rowa = (uint32_t)(wm * 32 + mi * 16 + arow_off) * HROWB + achunk;
                ldsm4(ah[mi][0], ah[mi][1], ah[mi][2], ah[mi][3], st + OFF_AH + rowa);
            }
            const int brow_off = (lane & 7) + ((lane >> 4) << 3);
            const uint32_t bchunk = kb + (((lane >> 3) & 1) << 4);
#pragma unroll
            for (int p = 0; p < 4; ++p) {
                uint32_t rowb = (uint32_t)(wn * 64 + p * 16 + brow_off) * HROWB + bchunk;
                ldsm4(bh[2 * p][0], bh[2 * p][1], bh[2 * p + 1][0], bh[2 * p + 1][1],
                      st + OFF_BH + rowb);
            }
#pragma unroll
            for (int mi = 0; mi < 2; ++mi)
#pragma unroll
                for (int ni = 0; ni < 8; ++ni)
                    mma16816(acc[mi][ni], ah[mi], bh[ni]);
        }
    };

    LOADR(0);
    STORER(0);
    __syncthreads();
    for (int c = 0; c < ncr; ++c) {
        if (c + 1 < ncr) LOADR(c + 1);
        COMPUTE(c & 1);
        if (c + 1 < ncr) STORER((c + 1) & 1);
        __syncthreads();
    }

    const int g = lane >> 2, tg = lane & 3;
    if (MODE == 0) {
        float* Op = (float*)Out_ + (size_t)b * smlS;
#pragma unroll
        for (int mi = 0; mi < 2; ++mi)
#pragma unroll
            for (int ni = 0; ni < 8; ++ni) {
                int row = i0 + wm * 32 + mi * 16 + g;
                int col = j0 + wn * 64 + ni * 8 + tg * 2;
                *(float2*)(Op + (size_t)row * CC + col) =
                    make_float2(acc[mi][ni][0], acc[mi][ni][1]);
                *(float2*)(Op + (size_t)(row + 8) * CC + col) =
                    make_float2(acc[mi][ni][2], acc[mi][ni][3]);
            }
    } else if (MODE == 2) {
        // B-build, written fp16 (same rounding downstream consumers applied)
        __half* Op = (__half*)Out_ + (size_t)b * bigS;
        const float aSc = fabsf(lr[b]) * s_lr[0];
        const float* E1 = E1_ + (size_t)b * bigS;
        const float* E2 = E2_ + (size_t)b * bigS;
        const float* Mf = Agf;
#pragma unroll
        for (int mi = 0; mi < 2; ++mi)
#pragma unroll
            for (int ni = 0; ni < 8; ++ni) {
                int row = i0 + wm * 32 + mi * 16 + g;
                int col = j0 + wn * 64 + ni * 8 + tg * 2;
#pragma unroll
                for (int h = 0; h < 2; ++h) {
                    size_t o = (size_t)(row + 8 * h) * CC + col;
                    float2 mv = *(const float2*)(Mf + o);
                    float2 uv = *(const float2*)(E1 + o);
                    float2 gv = *(const float2*)(E2 + o);
                    float rx = mv.x + aSc * (acc[mi][ni][2 * h + 0] - uv.x - gv.x);
                    float ry = mv.y + aSc * (acc[mi][ni][2 * h + 1] - uv.y - gv.y);
                    *(uint32_t*)(Op + o) = rnd2(rx, ry);
                }
            }
    } else {
        float* Op = (float*)Out_ + (size_t)b * bigS;
        const int TP = 132;
        float* T = (float*)dsm;   // needs 67584 B <= GEMM_SMEM
#pragma unroll
        for (int mi = 0; mi < 2; ++mi)
#pragma unroll
            for (int ni = 0; ni < 8; ++ni) {
                int ml = wm * 32 + mi * 16 + g;
                int nl = wn * 64 + ni * 8 + tg * 2;
                T[nl * TP + ml]           = acc[mi][ni][0];
                T[(nl + 1) * TP + ml]     = acc[mi][ni][1];
                T[nl * TP + ml + 8]       = acc[mi][ni][2];
                T[(nl + 1) * TP + ml + 8] = acc[mi][ni][3];
            }
        __syncthreads();
        int n = tid >> 1, sh = (tid & 1) * 64;
        const float* src = T + n * TP + sh;
        float* dst = Op + (size_t)(j0 + n) * RR + i0 + sh;
#pragma unroll
        for (int q = 0; q < 16; ++q)
            *(float4*)(dst + q * 4) = *(const float4*)(src + q * 4);
    }
}

// ---------------------------------------------------------------------------
// Symmetrize: Asym = 0.5*(A + A^T), fp32 in -> fp16 out
// ---------------------------------------------------------------------------
__global__ void k_sym(const float* __restrict__ A, __half* __restrict__ Asym) {
    int idx = blockIdx.x * 256 + threadIdx.x;
    int b = idx >> 16;
    int rem = idx & 65535;
    int i = rem >> 8, j = rem & 255;
    size_t base = (size_t)b * 65536;
    Asym[base + rem] = __float2half_rn(
        0.5f * (A[base + i * 256 + j] + A[base + j * 256 + i]));
}

// ---------------------------------------------------------------------------
// Blocked Cholesky (panel=32) + blocked triangular inverse (packed lower).
// V written fp16 (only consumed as a GEMM6 MMA operand).
// ---------------------------------------------------------------------------
__device__ __forceinline__ int tri(int r) { return (r * (r + 1)) >> 1; }

static constexpr int CHOL_SMEM = (32896 + 8704) * 4;
static constexpr int CTH = 512;

__global__ void __launch_bounds__(CTH, 1)
k_cholinv(const float* __restrict__ S, __half* __restrict__ V)
{
    extern __shared__ float sm[];
    float* Lp = sm;
    float* P  = sm + 32896;

    const int b = blockIdx.x;
    const int tid = threadIdx.x;
    const float* Sp = S + (size_t)b * 65536;

    {
        const int t2 = tid & 255, gpar = tid >> 8;
        for (int i = gpar; i < 256; i += 2)
            if (t2 <= i) Lp[tri(i) + t2] = Sp[(size_t)i * 256 + t2];
    }
    __syncthreads();

    for (int p = 0; p < 8; ++p) {
        const int c0 = 32 * p, rows = 256 - c0;

        for (int idx = tid; idx < rows * 32; idx += CTH) {
            int lr = idx >> 5, c = idx & 31;
            int r = c0 + lr, gc = c0 + c;
            P[lr * 34 + c] = (gc <= r) ? Lp[tri(r) + gc] : 0.0f;
        }
        __syncthreads();

        if (tid < 32) {
            const int ln = tid;
            for (int j = 0; j < 32; ++j) {
                if (ln == j) P[j * 34 + j] = sqrtf(P[j * 34 + j]);
                __syncwarp();
                float d = P[j * 34 + j];
                if (ln > j) P[ln * 34 + j] /= d;
                __syncwarp();
                if (ln > j) {
                    float lij = P[ln * 34 + j];
                    for (int k = j + 1; k <= ln; ++k)
                        P[ln * 34 + k] -= lij * P[k * 34 + j];
                }
                __syncwarp();
            }
        }
        __syncthreads();

        {
            int nr = rows - 32;
            if (tid < nr) {
                int lr = 32 + tid;
                float x[32];
#pragma unroll
                for (int c = 0; c < 32; ++c) x[c] = P[lr * 34 + c];
#pragma unroll
                for (int j = 0; j < 32; ++j) {
                    float s = x[j];
#pragma unroll
                    for (int k = 0; k < j; ++k) s -= x[k] * P[j * 34 + k];
                    x[j] = s / P[j * 34 + j];
                }
                int rb = tri(c0 + lr) + c0;
#pragma unroll
                for (int c = 0; c < 32; ++c) { P[lr * 34 + c] = x[c]; Lp[rb + c] = x[c]; }
            }
            if (tid < 32) {
                int rb = tri(c0 + tid) + c0;
                for (int c = 0; c <= tid; ++c) Lp[rb + c] = P[tid * 34 + c];
            }
        }
        __syncthreads();

        int T = rows - 32;
        if (T > 0) {
            int Tb = T >> 1;
            int ntask = (Tb * (Tb + 1)) >> 1;
            for (int t = tid; t < ntask; t += CTH) {
                int bi = (int)((sqrtf(8.0f * (float)t + 1.0f) - 1.0f) * 0.5f);
                while (((bi + 1) * (bi + 2)) / 2 <= t) ++bi;
                while ((bi * (bi + 1)) / 2 > t) --bi;
                int bj = t - (bi * (bi + 1)) / 2;
                int i0 = 32 + 2 * bi, j0 = 32 + 2 * bj;
                const float* Pi0 = P + i0 * 34;
                const float* Pi1 = Pi0 + 34;
                const float* Pj0 = P + j0 * 34;
                const float* Pj1 = Pj0 + 34;
                float a00 = 0, a01 = 0, a10 = 0, a11 = 0;
#pragma unroll
                for (int q = 0; q < 32; q += 2) {
                    float2 vi0 = *(const float2*)(Pi0 + q), vi1 = *(const float2*)(Pi1 + q);
                    float2 vj0 = *(const float2*)(Pj0 + q), vj1 = *(const float2*)(Pj1 + q);
                    a00 += vi0.x * vj0.x + vi0.y * vj0.y;
                    a01 += vi0.x * vj1.x + vi0.y * vj1.y;
                    a10 += vi1.x * vj0.x + vi1.y * vj0.y;
                    a11 += vi1.x * vj1.x + vi1.y * vj1.y;
                }
                int gr0 = c0 + i0, gr1 = gr0 + 1, gc0 = c0 + j0, gc1 = gc0 + 1;
                int rb0 = tri(gr0), rb1 = tri(gr1);
                Lp[rb0 + gc0] -= a00;
                if (bj < bi) Lp[rb0 + gc1] -= a01;
                Lp[rb1 + gc0] -= a10;
                Lp[rb1 + gc1] -= a11;
            }
        }
        __syncthreads();
    }

    {
        float wc[32];
        const bool act = tid < 256;
        if (act) {
            int w = tid >> 5, j = tid & 31;
            int g0 = 32 * w;
#pragma unroll
            for (int i = 0; i < 32; ++i) {
                int rb = tri(g0 + i) + g0;
                float acc = 0.0f;
#pragma unroll
                for (int k = 0; k < i; ++k) acc += Lp[rb + k] * wc[k];
                wc[i] = (((i == j) ? 1.0f : 0.0f) - acc) / Lp[rb + i];
            }
        }
        __syncthreads();
        if (act) {
            int w = tid >> 5, j = tid & 31;
            int g0 = 32 * w;
#pragma unroll
            for (int i = 0; i < 32; ++i)
                if (i >= j) Lp[tri(g0 + i) + g0 + j] = wc[i];
        }
    }
    __syncthreads();

    {
        int r = tid >> 4, tj = tid & 15;
        int cA = 2 * tj, cB = cA + 1;
        for (int J = 0; J < 8; ++J) {
            for (int I = J + 1; I < 8; ++I) {
                int lb = tri(32 * I + r);
                float a0 = 0, a1 = 0;
                {
                    int la = lb + 32 * J;
#pragma unroll 8
                    for (int k = 0; k < 32; ++k) {
                        float x = Lp[la + k];
                        int wb = tri(32 * J + k) + 32 * J;
                        float y0 = (k >= cA) ? Lp[wb + cA] : 0.0f;
                        float y1 = (k >= cB) ? Lp[wb + cB] : 0.0f;
                        a0 += x * y0; a1 += x * y1;
                    }
                }
                for (int K = J + 1; K < I; ++K) {
                    int la = lb + 32 * K;
#pragma unroll 8
                    for (int k = 0; k < 32; ++k) {
                        float x = Lp[la + k];
                        int wb = tri(32 * K + k) + 32 * J;
                        a0 += x * Lp[wb + cA];
                        a1 += x * Lp[wb + cB];
                    }
                }
                P[r * 33 + cA] = a0;
                P[r * 33 + cB] = a1;
                __syncthreads();
                float b0 = 0, b1 = 0;
                int db = lb + 32 * I;
                for (int k = 0; k <= r; ++k) {
                    float w = Lp[db + k];
                    b0 += w * P[k * 33 + cA];
                    b1 += w * P[k * 33 + cB];
                }
                Lp[lb + 32 * J + cA] = -b0;
                Lp[lb + 32 * J + cB] = -b1;
                __syncthreads();
            }
        }
    }

    __half* Vp = V + (size_t)b * 65536;
    for (int idx = tid; idx < CC * CC; idx += CTH) {
        int k = idx >> 8, c = idx & 255;
        Vp[idx] = (c >= k) ? __float2half_rn(Lp[tri(c) + k]) : __float2half_rn(0.0f);
    }
}

// ---------------------------------------------------------------------------
// Streams/events for batch-group pipelining (host objects only; no device mem).
// ---------------------------------------------------------------------------
static cudaStream_t g_strm[NGRP] = {};
static cudaEvent_t  g_evFork = nullptr;
static cudaEvent_t  g_evJoin[NGRP] = {};
static int g_stream_init = [](){
    for (int i = 1; i < NGRP; ++i)
        cudaStreamCreateWithFlags(&g_strm[i], cudaStreamNonBlocking);
    cudaEventCreateWithFlags(&g_evFork, cudaEventDisableTiming);
    for (int i = 1; i < NGRP; ++i)
        cudaEventCreateWithFlags(&g_evJoin[i], cudaEventDisableTiming);
    return 1;
}();

extern "C" void kernel_launch(void* const* d_in, const int* in_sizes, int n_in,
                              void* d_out, int out_size)
{
    const float* M    = (const float*)d_in[0];
    const float* Mg   = (const float*)d_in[1];
    const float* Up   = (const float*)d_in[2];
    const float* lr   = (const float*)d_in[3];
    const float* s_lr = (const float*)d_in[4];
    float* out = (float*)d_out;

    if (!g_strm[1]) {
        for (int i = 1; i < NGRP; ++i)
            cudaStreamCreateWithFlags(&g_strm[i], cudaStreamNonBlocking);
        cudaEventCreateWithFlags(&g_evFork, cudaEventDisableTiming);
        for (int i = 1; i < NGRP; ++i)
            cudaEventCreateWithFlags(&g_evJoin[i], cudaEventDisableTiming);
    }

    float *gA;
    __half *gAs, *gBh, *gVh;
    cudaGetSymbolAddress((void**)&gA, g_A);
    cudaGetSymbolAddress((void**)&gAs, g_As);
    cudaGetSymbolAddress((void**)&gBh, g_Bh);
    cudaGetSymbolAddress((void**)&gVh, g_Vh);

    cudaFuncSetAttribute(k_cholinv, cudaFuncAttributeMaxDynamicSharedMemorySize, CHOL_SMEM);
    cudaFuncSetAttribute(k_gemm<0, RR, false, false, false>,
                         cudaFuncAttributeMaxDynamicSharedMemorySize, GEMM_SMEM);
    cudaFuncSetAttribute(k_gemm<0, RR, true, true, true>,
                         cudaFuncAttributeMaxDynamicSharedMemorySize, GEMM_SMEM);
    cudaFuncSetAttribute(k_gemm<2, CC, false, false, true>,
                         cudaFuncAttributeMaxDynamicSharedMemorySize, GEMM_SMEM);
    cudaFuncSetAttribute(k_gemm<3, CC, false, true, true>,
                         cudaFuncAttributeMaxDynamicSharedMemorySize, GEMM_SMEM);

    const size_t bigS = (size_t)RR * CC, smlS = (size_t)CC * CC;
    dim3 blk(256);

    cudaEventRecord(g_evFork, 0);
    for (int i = 1; i < NGRP; ++i)
        cudaStreamWaitEvent(g_strm[i], g_evFork, 0);

    for (int gi = 0; gi < NGRP; ++gi) {
        cudaStream_t st = (gi == 0) ? (cudaStream_t)0 : g_strm[gi];
        const size_t ob = (size_t)gi * GB;
        const float* M_  = M  + ob * bigS;
        const float* Mg_ = Mg + ob * bigS;
        const float* U_  = Up + ob * bigS;
        const float* lr_ = lr + ob;
        float*  gA_  = gA  + ob * smlS;
        __half* gAs_ = gAs + ob * smlS;
        __half* gBh_ = gBh + ob * bigS;
        __half* gVh_ = gVh + ob * smlS;
        float*  out_ = out + ob * bigS;

        // 1) A = M^T Graw (fp32 in, fp32 out)
        k_gemm<0, RR, false, false, false><<<dim3(2, 2, GB), blk, GEMM_SMEM, st>>>(
            M_, Mg_, nullptr, nullptr, lr_, s_lr, gA_);
        // 2) Asym = 0.5*(A + A^T) -> fp16
        k_sym<<<(GB * 65536) / 256, blk, 0, st>>>(gA_, gAs_);
        // 3) B = M + a*(M@Asym - U - Graw) -> fp16
        k_gemm<2, CC, false, false, true><<<dim3(2, 18, GB), blk, GEMM_SMEM, st>>>(
            M_, gAs_, U_, Mg_, lr_, s_lr, gBh_);
        // 4) S = B^T B (both operands fp16, lower tiles only, fp32 out)
        k_gemm<0, RR, true, true, true><<<dim3(3, 1, GB), blk, GEMM_SMEM, st>>>(
            gBh_, gBh_, nullptr, nullptr, lr_, s_lr, gA_);
        // 5) blocked Cholesky + triangular inverse -> V = R^{-1} (fp16)
        k_cholinv<<<GB, CTH, CHOL_SMEM, st>>>(gA_, gVh_);
        // 6) out[b][c][r] = sum_k B[r][k] V[k][c] (fp16 operands, fp32 out)
        k_gemm<3, CC, false, true, true><<<dim3(2, 18, GB), blk, GEMM_SMEM, st>>>(
            gBh_, gVh_, nullptr, nullptr, lr_, s_lr, out_);
    }

    for (int i = 1; i < NGRP; ++i) {
        cudaEventRecord(g_evJoin[i], g_strm[i]);
        cudaStreamWaitEvent((cudaStream_t)0, g_evJoin[i], 0);
    }
}